// round 1
// baseline (speedup 1.0000x reference)
#include <cuda_runtime.h>
#include <cuda_bf16.h>
#include <cstdint>

// ContrastiveLoss: B=8192, D=128, T=0.1, classes c=2*tt+tp in {0..3}
//   logits_ij = (f_i . f_j) / (|f_i||f_j| * T)   (eps clamp never binds for these inputs)
//   pos class of row i = c_i ^ 1, neg class = c_i ^ 2
//   row loss = (L_pos - pcnt*log(E_pos+E_neg)) / pcnt   (if pcnt>0 && ncnt>0)
//   loss = -sum(rowloss)/B

#define B_SZ 8192
#define D_SZ 128
#define M_TILE 64
#define N_TILE 64

__device__ __align__(256) float g_GT[D_SZ * B_SZ];   // k-major scaled features: GT[k][j]
__device__ int   g_cls[B_SZ];
__device__ int   g_cnt4[4];
__device__ float g_rowval[B_SZ];
__device__ int   g_is64;

// ---------------------------------------------------------------- detect int width
__global__ void detect_kernel(const long long* __restrict__ dix64) {
    // Read first 4096 int64 (= exactly 32KB = the int32 buffer size, so no OOB
    // in either case). If every value is in [0, 100000) the layout is int64;
    // an int32 buffer reinterpreted as int64 has random high words -> out of range.
    __shared__ int bad;
    if (threadIdx.x == 0) bad = 0;
    __syncthreads();
    int local = 0;
    for (int i = threadIdx.x; i < 4096; i += blockDim.x) {
        long long v = dix64[i];
        if (v < 0 || v >= 100000) local = 1;
    }
    if (local) atomicOr(&bad, 1);
    __syncthreads();
    if (threadIdx.x == 0) g_is64 = (bad == 0) ? 1 : 0;
}

// ---------------------------------------------------------------- prep: norms, scale, class
__global__ void prep_kernel(const float* __restrict__ F,
                            const void* __restrict__ data_ix,
                            const void* __restrict__ tt,
                            const void* __restrict__ tp) {
    const float INV_SQRT_T = 3.1622776601683795f;  // 1/sqrt(0.1)
    int warp = (blockIdx.x * blockDim.x + threadIdx.x) >> 5;
    int lane = threadIdx.x & 31;
    if (warp >= B_SZ) return;
    const float* row = F + (size_t)warp * D_SZ;
    float v0 = row[lane], v1 = row[lane + 32], v2 = row[lane + 64], v3 = row[lane + 96];
    float ss = v0 * v0 + v1 * v1 + v2 * v2 + v3 * v3;
#pragma unroll
    for (int o = 16; o; o >>= 1) ss += __shfl_xor_sync(0xffffffffu, ss, o);
    float scale = INV_SQRT_T / sqrtf(ss);
    g_GT[(lane      ) * B_SZ + warp] = v0 * scale;
    g_GT[(lane + 32 ) * B_SZ + warp] = v1 * scale;
    g_GT[(lane + 64 ) * B_SZ + warp] = v2 * scale;
    g_GT[(lane + 96 ) * B_SZ + warp] = v3 * scale;
    if (lane == 0) {
        long long ix;
        int t, p;
        if (g_is64) {
            ix = ((const long long*)data_ix)[warp];
            t = (int)((const long long*)tt)[ix];
            p = (int)((const long long*)tp)[ix];
        } else {
            ix = (long long)((const int*)data_ix)[warp];
            t = ((const int*)tt)[ix];
            p = ((const int*)tp)[ix];
        }
        g_cls[warp] = t * 2 + p;
    }
}

// ---------------------------------------------------------------- class histogram
__global__ void hist_kernel() {
    __shared__ int c[4];
    if (threadIdx.x < 4) c[threadIdx.x] = 0;
    __syncthreads();
    int lc0 = 0, lc1 = 0, lc2 = 0, lc3 = 0;
    for (int i = threadIdx.x; i < B_SZ; i += blockDim.x) {
        int cl = g_cls[i];
        lc0 += (cl == 0); lc1 += (cl == 1); lc2 += (cl == 2); lc3 += (cl == 3);
    }
    atomicAdd(&c[0], lc0); atomicAdd(&c[1], lc1);
    atomicAdd(&c[2], lc2); atomicAdd(&c[3], lc3);
    __syncthreads();
    if (threadIdx.x < 4) g_cnt4[threadIdx.x] = c[threadIdx.x];
}

// ---------------------------------------------------------------- fused GEMM + masked softmax sums
// Grid: B/M_TILE = 128 blocks, 256 threads. Each block: 64 rows x all 8192 cols.
// Dyn smem: As[128][64] (k-major), Bs[128][64] (k-major), clsS[64].
__global__ void __launch_bounds__(256) main_kernel() {
    extern __shared__ float sm[];
    float* As = sm;                       // 128*64 floats
    float* Bs = sm + D_SZ * M_TILE;       // 128*64 floats
    int*   clsS = (int*)(sm + 2 * D_SZ * M_TILE);  // 64 ints

    const int tid = threadIdx.x;
    const int ibase = blockIdx.x * M_TILE;
    const int tx = tid & 15, ty = tid >> 4;
    const int i0 = ty * 4, j0 = tx * 4;

    // load A tile: As[k][i] <- GT[k][ibase+i]  (coalesced, float4)
#pragma unroll
    for (int it = 0; it < 8; ++it) {
        int idx = tid + it * 256;            // 2048 float4 total
        int k = idx >> 4, i4 = idx & 15;
        float4 v = *(const float4*)(&g_GT[(size_t)k * B_SZ + ibase + i4 * 4]);
        *(float4*)(&As[k * M_TILE + i4 * 4]) = v;
    }

    float epos[4] = {0.f, 0.f, 0.f, 0.f};
    float eneg[4] = {0.f, 0.f, 0.f, 0.f};
    float lsum[4] = {0.f, 0.f, 0.f, 0.f};
    int pc[4], nc[4];
#pragma unroll
    for (int r = 0; r < 4; ++r) {
        int ci = g_cls[ibase + i0 + r];
        pc[r] = ci ^ 1;
        nc[r] = ci ^ 2;
    }

    const float4* As4 = (const float4*)As;
    const float4* Bs4 = (const float4*)Bs;

    for (int jt = 0; jt < B_SZ / N_TILE; ++jt) {
        const int jbase = jt * N_TILE;
        __syncthreads();   // previous tile fully consumed
#pragma unroll
        for (int it = 0; it < 8; ++it) {
            int idx = tid + it * 256;
            int k = idx >> 4, i4 = idx & 15;
            float4 v = *(const float4*)(&g_GT[(size_t)k * B_SZ + jbase + i4 * 4]);
            *(float4*)(&Bs[k * N_TILE + i4 * 4]) = v;
        }
        if (tid < N_TILE) clsS[tid] = g_cls[jbase + tid];
        __syncthreads();

        float c00 = 0.f, c01 = 0.f, c02 = 0.f, c03 = 0.f;
        float c10 = 0.f, c11 = 0.f, c12 = 0.f, c13 = 0.f;
        float c20 = 0.f, c21 = 0.f, c22 = 0.f, c23 = 0.f;
        float c30 = 0.f, c31 = 0.f, c32 = 0.f, c33 = 0.f;
#pragma unroll 4
        for (int k = 0; k < D_SZ; ++k) {
            float4 a = As4[k * 16 + ty];
            float4 b = Bs4[k * 16 + tx];
            c00 += a.x * b.x; c01 += a.x * b.y; c02 += a.x * b.z; c03 += a.x * b.w;
            c10 += a.y * b.x; c11 += a.y * b.y; c12 += a.y * b.z; c13 += a.y * b.w;
            c20 += a.z * b.x; c21 += a.z * b.y; c22 += a.z * b.z; c23 += a.z * b.w;
            c30 += a.w * b.x; c31 += a.w * b.y; c32 += a.w * b.z; c33 += a.w * b.w;
        }

        int cj0 = clsS[j0 + 0], cj1 = clsS[j0 + 1], cj2 = clsS[j0 + 2], cj3 = clsS[j0 + 3];
        float cr[4][4] = {{c00, c01, c02, c03}, {c10, c11, c12, c13},
                          {c20, c21, c22, c23}, {c30, c31, c32, c33}};
        int cj[4] = {cj0, cj1, cj2, cj3};
#pragma unroll
        for (int r = 0; r < 4; ++r) {
#pragma unroll
            for (int s = 0; s < 4; ++s) {
                float l = cr[r][s];
                float e = __expf(l);
                bool isp = (cj[s] == pc[r]);
                bool isn = (cj[s] == nc[r]);
                epos[r] += isp ? e : 0.f;
                lsum[r] += isp ? l : 0.f;
                eneg[r] += isn ? e : 0.f;
            }
        }
    }

    // deterministic cross-tx reduction (reuse Bs region)
    __syncthreads();
    float* red = Bs;  // [64 rows][16 tx][3]
#pragma unroll
    for (int r = 0; r < 4; ++r) {
        int row = i0 + r;
        red[(row * 16 + tx) * 3 + 0] = epos[r];
        red[(row * 16 + tx) * 3 + 1] = eneg[r];
        red[(row * 16 + tx) * 3 + 2] = lsum[r];
    }
    __syncthreads();
    if (tid < M_TILE) {
        float Ep = 0.f, En = 0.f, Ls = 0.f;
#pragma unroll
        for (int t = 0; t < 16; ++t) {
            Ep += red[(tid * 16 + t) * 3 + 0];
            En += red[(tid * 16 + t) * 3 + 1];
            Ls += red[(tid * 16 + t) * 3 + 2];
        }
        int i = ibase + tid;
        int ci = g_cls[i];
        int pcnt = g_cnt4[ci ^ 1];
        int ncnt = g_cnt4[ci ^ 2];
        float val = 0.f;
        if (pcnt > 0 && ncnt > 0)
            val = (Ls - (float)pcnt * logf(Ep + En)) / (float)pcnt;
        g_rowval[i] = val;
    }
}

// ---------------------------------------------------------------- final reduce
__global__ void final_kernel(float* __restrict__ out) {
    __shared__ float s[256];
    float acc = 0.f;
    for (int i = threadIdx.x; i < B_SZ; i += 256) acc += g_rowval[i];
    s[threadIdx.x] = acc;
    __syncthreads();
    for (int o = 128; o; o >>= 1) {
        if (threadIdx.x < o) s[threadIdx.x] += s[threadIdx.x + o];
        __syncthreads();
    }
    if (threadIdx.x == 0) out[0] = -s[0] / (float)B_SZ;
}

// ---------------------------------------------------------------- launch
extern "C" void kernel_launch(void* const* d_in, const int* in_sizes, int n_in,
                              void* d_out, int out_size) {
    const float* F = (const float*)d_in[0];
    const void* dix = d_in[1];
    const void* tt  = d_in[2];
    const void* tp  = d_in[3];
    float* out = (float*)d_out;

    detect_kernel<<<1, 256>>>((const long long*)dix);
    prep_kernel<<<(B_SZ * 32) / 256, 256>>>(F, dix, tt, tp);
    hist_kernel<<<1, 256>>>();

    int smem = (2 * D_SZ * M_TILE) * (int)sizeof(float) + N_TILE * (int)sizeof(int);
    cudaFuncSetAttribute(main_kernel, cudaFuncAttributeMaxDynamicSharedMemorySize, smem);
    main_kernel<<<B_SZ / M_TILE, 256, smem>>>();

    final_kernel<<<1, 256>>>(out);
}

// round 3
// speedup vs baseline: 3.2314x; 3.2314x over previous
#include <cuda_runtime.h>
#include <cuda_bf16.h>
#include <cstdint>

// ContrastiveLoss B=8192 D=128 T=0.1, classes c=2*tt+tp in {0..3}
// mma.sync (HMMA) bf16 3-split path, compute_103-safe (no tcgen05 / no 'a' features).
// g = f * sqrt(log2e/T)/||f||;  logit(log2) = g_i . g_j = HH + HL + LH (+LL dropped)

#define B_SZ 8192
#define NJT  32              // j-tiles per CTA (4096 cols / 128)
#define RSB  272u            // smem row stride bytes (136 bf16: 128 data + 8 pad)
#define OFF_AH 0u
#define OFF_AL 34816u        // 128*272
#define OFF_B  69632u        // + buf*69632 ; hi at +0, lo at +34816
#define OFF_CLS 208896u      // 4096 class bytes (this CTA's col half)
#define OFF_RED 69632u       // epilogue reduce scratch (reuses B area)
#define SMEM_BYTES (212992 + 1024)

// ---------------------------------------------------------------- globals
__device__ __align__(256) __nv_bfloat16 g_hi[B_SZ * 128];
__device__ __align__(256) __nv_bfloat16 g_lo[B_SZ * 128];
__device__ int           g_cls[B_SZ];
__device__ unsigned char g_clsb[B_SZ];
__device__ int           g_cnt4[4];
__device__ float4        g_part[2][B_SZ];
__device__ int           g_is64;

// ---------------------------------------------------------------- helpers
__device__ __forceinline__ uint32_t smem_u32(const void* p) {
    uint32_t a;
    asm("{ .reg .u64 t; cvta.to.shared.u64 t, %1; cvt.u32.u64 %0, t; }" : "=r"(a) : "l"(p));
    return a;
}
__device__ __forceinline__ void cp16(uint32_t dst, const void* src) {
    asm volatile("cp.async.cg.shared.global [%0], [%1], 16;" :: "r"(dst), "l"(src) : "memory");
}
__device__ __forceinline__ void cp_commit() {
    asm volatile("cp.async.commit_group;" ::: "memory");
}
__device__ __forceinline__ void cp_wait0() {
    asm volatile("cp.async.wait_group 0;" ::: "memory");
}
__device__ __forceinline__ void cp_wait1() {
    asm volatile("cp.async.wait_group 1;" ::: "memory");
}
__device__ __forceinline__ void ldsm4(uint32_t* r, uint32_t addr) {
    asm volatile("ldmatrix.sync.aligned.m8n8.x4.shared.b16 {%0,%1,%2,%3}, [%4];"
                 : "=r"(r[0]), "=r"(r[1]), "=r"(r[2]), "=r"(r[3]) : "r"(addr));
}
__device__ __forceinline__ void mma_bf16(float* c, const uint32_t* a, uint32_t b0, uint32_t b1) {
    asm volatile(
        "mma.sync.aligned.m16n8k16.row.col.f32.bf16.bf16.f32 "
        "{%0,%1,%2,%3}, {%4,%5,%6,%7}, {%8,%9}, {%0,%1,%2,%3};"
        : "+f"(c[0]), "+f"(c[1]), "+f"(c[2]), "+f"(c[3])
        : "r"(a[0]), "r"(a[1]), "r"(a[2]), "r"(a[3]), "r"(b0), "r"(b1));
}
__device__ __forceinline__ float ex2f(float v) {
    float e;
    asm("ex2.approx.ftz.f32 %0, %1;" : "=f"(e) : "f"(v));
    return e;
}

// load one hi+lo tile pair (128 rows x 256B each) into smem (padded rows)
__device__ __forceinline__ void load_tile(uint32_t sdst_h, int rowbase, int tid) {
#pragma unroll
    for (int i = 0; i < 8; ++i) {
        int idx = tid + i * 256;             // 0..2047
        int r = idx >> 4, c = idx & 15;
        uint32_t dst = sdst_h + (uint32_t)r * RSB + (uint32_t)c * 16u;
        const __nv_bfloat16* sh = g_hi + (size_t)(rowbase + r) * 128 + c * 8;
        const __nv_bfloat16* sl = g_lo + (size_t)(rowbase + r) * 128 + c * 8;
        cp16(dst, sh);
        cp16(dst + 34816u, sl);
    }
}

// ---------------------------------------------------------------- detect int width
__global__ void detect_kernel(const long long* __restrict__ dix64) {
    __shared__ int bad;
    if (threadIdx.x == 0) bad = 0;
    __syncthreads();
    int local = 0;
    for (int i = threadIdx.x; i < 4096; i += blockDim.x) {
        long long v = dix64[i];
        if (v < 0 || v >= 100000) local = 1;
    }
    if (local) atomicOr(&bad, 1);
    __syncthreads();
    if (threadIdx.x == 0) g_is64 = (bad == 0) ? 1 : 0;
}

// ---------------------------------------------------------------- prep
__global__ void prep_kernel(const float* __restrict__ F,
                            const void* __restrict__ data_ix,
                            const void* __restrict__ tt,
                            const void* __restrict__ tp) {
    int warp = (blockIdx.x * blockDim.x + threadIdx.x) >> 5;
    int lane = threadIdx.x & 31;
    if (warp >= B_SZ) return;
    const float* row = F + (size_t)warp * 128;
    float v0 = row[lane], v1 = row[lane + 32], v2 = row[lane + 64], v3 = row[lane + 96];
    float ss = v0 * v0 + v1 * v1 + v2 * v2 + v3 * v3;
#pragma unroll
    for (int o = 16; o; o >>= 1) ss += __shfl_xor_sync(0xffffffffu, ss, o);
    float scale = sqrtf(14.4269504088896f) / sqrtf(ss);   // sqrt(log2e / T)
    float g[4] = {v0 * scale, v1 * scale, v2 * scale, v3 * scale};
#pragma unroll
    for (int q = 0; q < 4; ++q) {
        __nv_bfloat16 h = __float2bfloat16(g[q]);
        __nv_bfloat16 lo = __float2bfloat16(g[q] - __bfloat162float(h));
        g_hi[(size_t)warp * 128 + lane + q * 32] = h;
        g_lo[(size_t)warp * 128 + lane + q * 32] = lo;
    }
    if (lane == 0) {
        long long ix;
        int t, p;
        if (g_is64) {
            ix = ((const long long*)data_ix)[warp];
            t = (int)((const long long*)tt)[ix];
            p = (int)((const long long*)tp)[ix];
        } else {
            ix = (long long)((const int*)data_ix)[warp];
            t = ((const int*)tt)[ix];
            p = ((const int*)tp)[ix];
        }
        int cls = t * 2 + p;
        g_cls[warp] = cls;
        g_clsb[warp] = (unsigned char)cls;
    }
}

// ---------------------------------------------------------------- hist
__global__ void hist_kernel() {
    __shared__ int c[4];
    if (threadIdx.x < 4) c[threadIdx.x] = 0;
    __syncthreads();
    int lc0 = 0, lc1 = 0, lc2 = 0, lc3 = 0;
    for (int i = threadIdx.x; i < B_SZ; i += blockDim.x) {
        int cl = g_cls[i];
        lc0 += (cl == 0); lc1 += (cl == 1); lc2 += (cl == 2); lc3 += (cl == 3);
    }
    atomicAdd(&c[0], lc0); atomicAdd(&c[1], lc1);
    atomicAdd(&c[2], lc2); atomicAdd(&c[3], lc3);
    __syncthreads();
    if (threadIdx.x < 4) g_cnt4[threadIdx.x] = c[threadIdx.x];
}

// ---------------------------------------------------------------- main kernel
// grid (64, 2): 64 M-tiles x 2 col halves. 256 threads = 8 warps (4m x 2n),
// warp tile 32x64. A(hi,lo) persistent in smem; B double-buffered cp.async.
__global__ void __launch_bounds__(256, 1) main_kernel() {
    extern __shared__ char smraw[];
    char* smp = (char*)(((uintptr_t)smraw + 1023) & ~(uintptr_t)1023);
    const uint32_t sb = smem_u32(smp);

    const int tid = threadIdx.x;
    const int l = tid & 31, wid = tid >> 5;
    const int warp_m = wid >> 1, warp_n = wid & 1;
    const int ibase = blockIdx.x * 128;
    const int colbase = blockIdx.y * 4096;

    // column class bytes for this CTA's 4096 cols
    ((uint4*)(smp + OFF_CLS))[tid] = ((const uint4*)(g_clsb + colbase))[tid];

    // A tile (persistent) + B tile 0 : group 0
    load_tile(sb + OFF_AH, ibase, tid);
    load_tile(sb + OFF_B, colbase, tid);
    cp_commit();

    // per-lane ldmatrix base addresses
    const uint32_t laneA = (uint32_t)((warp_m * 32 + (l & 15)) * (int)RSB + ((l >> 4) * 16));
    const uint32_t pAh = sb + OFF_AH + laneA;
    const uint32_t pAl = sb + OFF_AL + laneA;
    const uint32_t laneB = (uint32_t)((warp_n * 64 + (l & 15)) * (int)RSB + ((l >> 4) * 16));

    // row classes (fixed per lane): rows warp_m*32 + (l>>2) + {0,8,16,24}
    int pc[4], ncl[4];
    {
        int r0 = ibase + warp_m * 32 + (l >> 2);
#pragma unroll
        for (int ri = 0; ri < 4; ++ri) {
            int cr = g_cls[r0 + ri * 8];
            pc[ri] = cr ^ 1;
            ncl[ri] = cr ^ 2;
        }
    }

    float epos[4] = {0.f, 0.f, 0.f, 0.f};
    float eneg[4] = {0.f, 0.f, 0.f, 0.f};
    float lsum[4] = {0.f, 0.f, 0.f, 0.f};

    for (int jt = 0; jt < NJT; ++jt) {
        const int buf = jt & 1;
        if (jt + 1 < NJT) {
            load_tile(sb + OFF_B + (uint32_t)(buf ^ 1) * 69632u, colbase + (jt + 1) * 128, tid);
            cp_commit();
            cp_wait1();
        } else {
            cp_wait0();
        }
        __syncthreads();

        const uint32_t pBh = sb + OFF_B + (uint32_t)buf * 69632u + laneB;
        const uint32_t pBl = pBh + 34816u;

        float acc[2][8][4];
#pragma unroll
        for (int mf = 0; mf < 2; ++mf)
#pragma unroll
            for (int nf = 0; nf < 8; ++nf)
#pragma unroll
                for (int q = 0; q < 4; ++q) acc[mf][nf][q] = 0.f;

#pragma unroll 1
        for (int ks = 0; ks < 8; ++ks) {
            const uint32_t ko = (uint32_t)ks * 32u;
            uint32_t aH[2][4], aL[2][4];
            ldsm4(aH[0], pAh + ko);
            ldsm4(aH[1], pAh + 16u * RSB + ko);
            ldsm4(aL[0], pAl + ko);
            ldsm4(aL[1], pAl + 16u * RSB + ko);
#pragma unroll
            for (int nf2 = 0; nf2 < 4; ++nf2) {
                uint32_t bh[4], bl[4];
                ldsm4(bh, pBh + (uint32_t)nf2 * 16u * RSB + ko);
                ldsm4(bl, pBl + (uint32_t)nf2 * 16u * RSB + ko);
#pragma unroll
                for (int mf = 0; mf < 2; ++mf) {
                    mma_bf16(acc[mf][nf2 * 2],     aH[mf], bh[0], bh[2]);
                    mma_bf16(acc[mf][nf2 * 2],     aH[mf], bl[0], bl[2]);
                    mma_bf16(acc[mf][nf2 * 2],     aL[mf], bh[0], bh[2]);
                    mma_bf16(acc[mf][nf2 * 2 + 1], aH[mf], bh[1], bh[3]);
                    mma_bf16(acc[mf][nf2 * 2 + 1], aH[mf], bl[1], bl[3]);
                    mma_bf16(acc[mf][nf2 * 2 + 1], aL[mf], bh[1], bh[3]);
                }
            }
        }

        // epilogue: masked log-domain sums (cols: jt*128 + warp_n*64 + nf*8 + 2(l&3) + {0,1})
#pragma unroll
        for (int nf = 0; nf < 8; ++nf) {
            uint32_t ca = sb + OFF_CLS +
                          (uint32_t)(jt * 128 + warp_n * 64 + nf * 8 + 2 * (l & 3));
            unsigned short cw;
            asm volatile("ld.shared.u16 %0, [%1];" : "=h"(cw) : "r"(ca));
            const int cj0 = cw & 0xff, cj1 = cw >> 8;
#pragma unroll
            for (int mf = 0; mf < 2; ++mf)
#pragma unroll
                for (int h = 0; h < 2; ++h) {
                    const int ri = mf * 2 + h;
                    float v0 = acc[mf][nf][h * 2 + 0];
                    float v1 = acc[mf][nf][h * 2 + 1];
                    float e0 = ex2f(v0), e1 = ex2f(v1);
                    if (cj0 == pc[ri]) { epos[ri] += e0; lsum[ri] += v0; }
                    else if (cj0 == ncl[ri]) { eneg[ri] += e0; }
                    if (cj1 == pc[ri]) { epos[ri] += e1; lsum[ri] += v1; }
                    else if (cj1 == ncl[ri]) { eneg[ri] += e1; }
                }
        }
        __syncthreads();
    }

    // reduce across the 4 lanes sharing each row (l&3), then across warp_n
#pragma unroll
    for (int ri = 0; ri < 4; ++ri) {
        epos[ri] += __shfl_xor_sync(0xffffffffu, epos[ri], 1);
        epos[ri] += __shfl_xor_sync(0xffffffffu, epos[ri], 2);
        eneg[ri] += __shfl_xor_sync(0xffffffffu, eneg[ri], 1);
        eneg[ri] += __shfl_xor_sync(0xffffffffu, eneg[ri], 2);
        lsum[ri] += __shfl_xor_sync(0xffffffffu, lsum[ri], 1);
        lsum[ri] += __shfl_xor_sync(0xffffffffu, lsum[ri], 2);
    }
    float* red = (float*)(smp + OFF_RED);   // [128 rows][2 warp_n][3]
    if ((l & 3) == 0) {
#pragma unroll
        for (int ri = 0; ri < 4; ++ri) {
            int row = warp_m * 32 + (l >> 2) + ri * 8;
            red[(row * 2 + warp_n) * 3 + 0] = epos[ri];
            red[(row * 2 + warp_n) * 3 + 1] = eneg[ri];
            red[(row * 2 + warp_n) * 3 + 2] = lsum[ri];
        }
    }
    __syncthreads();
    if (tid < 128) {
        float Ep = red[(tid * 2) * 3 + 0] + red[(tid * 2 + 1) * 3 + 0];
        float En = red[(tid * 2) * 3 + 1] + red[(tid * 2 + 1) * 3 + 1];
        float Ls = red[(tid * 2) * 3 + 2] + red[(tid * 2 + 1) * 3 + 2];
        g_part[blockIdx.y][ibase + tid] = make_float4(Ep, En, Ls, 0.f);
    }
}

// ---------------------------------------------------------------- final reduce
__global__ void final_kernel(float* __restrict__ out) {
    __shared__ float s[256];
    const float LN2 = 0.6931471805599453f;
    float acc = 0.f;
    for (int i = threadIdx.x; i < B_SZ; i += 256) {
        float4 p0 = g_part[0][i];
        float4 p1 = g_part[1][i];
        float Ep = p0.x + p1.x;
        float En = p0.y + p1.y;
        float Ls = (p0.z + p1.z) * LN2;
        int ci = g_cls[i];
        int pcnt = g_cnt4[ci ^ 1];
        int ncnt = g_cnt4[ci ^ 2];
        if (pcnt > 0 && ncnt > 0)
            acc += (Ls - (float)pcnt * logf(Ep + En)) / (float)pcnt;
    }
    s[threadIdx.x] = acc;
    __syncthreads();
    for (int o = 128; o; o >>= 1) {
        if (threadIdx.x < o) s[threadIdx.x] += s[threadIdx.x + o];
        __syncthreads();
    }
    if (threadIdx.x == 0) out[0] = -s[0] / (float)B_SZ;
}

// ---------------------------------------------------------------- launch
extern "C" void kernel_launch(void* const* d_in, const int* in_sizes, int n_in,
                              void* d_out, int out_size) {
    const float* F = (const float*)d_in[0];
    const void* dix = d_in[1];
    const void* tt  = d_in[2];
    const void* tp  = d_in[3];
    float* out = (float*)d_out;

    detect_kernel<<<1, 256>>>((const long long*)dix);
    prep_kernel<<<(B_SZ * 32) / 256, 256>>>(F, dix, tt, tp);
    hist_kernel<<<1, 256>>>();

    cudaFuncSetAttribute(main_kernel, cudaFuncAttributeMaxDynamicSharedMemorySize, SMEM_BYTES);
    main_kernel<<<dim3(64, 2), 256, SMEM_BYTES>>>();

    final_kernel<<<1, 256>>>(out);
}

// round 4
// speedup vs baseline: 3.6924x; 1.1427x over previous
#include <cuda_runtime.h>
#include <cuda_bf16.h>
#include <cstdint>

// ContrastiveLoss B=8192 D=128 T=0.1, classes c=2*tt+tp in {0..3}
// Symmetric-pair HMMA bf16 3-split: only unordered 128x128 tile pairs computed;
// each off-diagonal tile feeds row sums (rows i) AND column sums (rows j),
// since x = cls_i^cls_j classifies both sides identically.

#define B_SZ 8192
#define RSB  272u            // smem row stride bytes (128 data bf16 + pad)
#define OFF_AH 0u
#define OFF_AL 34816u        // 128*272
#define OFF_B  69632u        // + buf*69632 ; hi at +0, lo at +34816
#define OFF_CLS 208896u      // + buf*128
#define OFF_RED 209152u      // 4*128*3 floats = 6144 B
#define SMEM_BYTES (209152 + 6144 + 1024)

// ---------------------------------------------------------------- globals
__device__ __align__(256) __nv_bfloat16 g_hi[B_SZ * 128];
__device__ __align__(256) __nv_bfloat16 g_lo[B_SZ * 128];
__device__ int           g_cls[B_SZ];
__device__ __align__(256) unsigned char g_clsb[B_SZ];
__device__ int           g_cnt4[4];
__device__ float4        g_rpart[16][B_SZ];   // row-side partials per q
__device__ float4        g_cpart[32][B_SZ];   // col-side partials per (d-1)
__device__ float         g_rowval[B_SZ];
__device__ int           g_is64;

// ---------------------------------------------------------------- helpers
__device__ __forceinline__ uint32_t smem_u32(const void* p) {
    uint32_t a;
    asm("{ .reg .u64 t; cvta.to.shared.u64 t, %1; cvt.u32.u64 %0, t; }" : "=r"(a) : "l"(p));
    return a;
}
__device__ __forceinline__ void cp16(uint32_t dst, const void* src) {
    asm volatile("cp.async.cg.shared.global [%0], [%1], 16;" :: "r"(dst), "l"(src) : "memory");
}
__device__ __forceinline__ void cp_commit() {
    asm volatile("cp.async.commit_group;" ::: "memory");
}
__device__ __forceinline__ void cp_wait0() {
    asm volatile("cp.async.wait_group 0;" ::: "memory");
}
__device__ __forceinline__ void cp_wait1() {
    asm volatile("cp.async.wait_group 1;" ::: "memory");
}
__device__ __forceinline__ void ldsm4(uint32_t* r, uint32_t addr) {
    asm volatile("ldmatrix.sync.aligned.m8n8.x4.shared.b16 {%0,%1,%2,%3}, [%4];"
                 : "=r"(r[0]), "=r"(r[1]), "=r"(r[2]), "=r"(r[3]) : "r"(addr));
}
__device__ __forceinline__ void mma_bf16(float* c, const uint32_t* a, uint32_t b0, uint32_t b1) {
    asm volatile(
        "mma.sync.aligned.m16n8k16.row.col.f32.bf16.bf16.f32 "
        "{%0,%1,%2,%3}, {%4,%5,%6,%7}, {%8,%9}, {%0,%1,%2,%3};"
        : "+f"(c[0]), "+f"(c[1]), "+f"(c[2]), "+f"(c[3])
        : "r"(a[0]), "r"(a[1]), "r"(a[2]), "r"(a[3]), "r"(b0), "r"(b1));
}
__device__ __forceinline__ float ex2f(float v) {
    float e;
    asm("ex2.approx.ftz.f32 %0, %1;" : "=f"(e) : "f"(v));
    return e;
}

// async load one hi+lo tile pair (128 rows x 256B) into padded smem rows
__device__ __forceinline__ void load_tile(uint32_t sdst_h, int rowbase, int tid) {
#pragma unroll
    for (int i = 0; i < 8; ++i) {
        int idx = tid + i * 256;
        int r = idx >> 4, c = idx & 15;
        uint32_t dst = sdst_h + (uint32_t)r * RSB + (uint32_t)c * 16u;
        cp16(dst, g_hi + (size_t)(rowbase + r) * 128 + c * 8);
        cp16(dst + 34816u, g_lo + (size_t)(rowbase + r) * 128 + c * 8);
    }
}

// ---------------------------------------------------------------- detect + init
__global__ void detect_kernel(const long long* __restrict__ dix64) {
    __shared__ int bad;
    if (threadIdx.x == 0) bad = 0;
    __syncthreads();
    int local = 0;
    for (int i = threadIdx.x; i < 4096; i += blockDim.x) {
        long long v = dix64[i];
        if (v < 0 || v >= 100000) local = 1;
    }
    if (local) atomicOr(&bad, 1);
    __syncthreads();
    if (threadIdx.x == 0) g_is64 = (bad == 0) ? 1 : 0;
    if (threadIdx.x < 4) g_cnt4[threadIdx.x] = 0;
}

// ---------------------------------------------------------------- prep (+hist)
__global__ void prep_kernel(const float* __restrict__ F,
                            const void* __restrict__ data_ix,
                            const void* __restrict__ tt,
                            const void* __restrict__ tp) {
    __shared__ int hc[4];
    if (threadIdx.x < 4) hc[threadIdx.x] = 0;
    __syncthreads();
    int warp = (blockIdx.x * blockDim.x + threadIdx.x) >> 5;
    int lane = threadIdx.x & 31;
    const float* row = F + (size_t)warp * 128;
    float v0 = row[lane], v1 = row[lane + 32], v2 = row[lane + 64], v3 = row[lane + 96];
    float ss = v0 * v0 + v1 * v1 + v2 * v2 + v3 * v3;
#pragma unroll
    for (int o = 16; o; o >>= 1) ss += __shfl_xor_sync(0xffffffffu, ss, o);
    float scale = sqrtf(14.4269504088896f) / sqrtf(ss);   // sqrt(log2e / T)
    float g[4] = {v0 * scale, v1 * scale, v2 * scale, v3 * scale};
#pragma unroll
    for (int qq = 0; qq < 4; ++qq) {
        __nv_bfloat16 h = __float2bfloat16(g[qq]);
        __nv_bfloat16 lo = __float2bfloat16(g[qq] - __bfloat162float(h));
        g_hi[(size_t)warp * 128 + lane + qq * 32] = h;
        g_lo[(size_t)warp * 128 + lane + qq * 32] = lo;
    }
    if (lane == 0) {
        long long ix;
        int t, p;
        if (g_is64) {
            ix = ((const long long*)data_ix)[warp];
            t = (int)((const long long*)tt)[ix];
            p = (int)((const long long*)tp)[ix];
        } else {
            ix = (long long)((const int*)data_ix)[warp];
            t = ((const int*)tt)[ix];
            p = ((const int*)tp)[ix];
        }
        int cls = t * 2 + p;
        g_cls[warp] = cls;
        g_clsb[warp] = (unsigned char)cls;
        atomicAdd(&hc[cls], 1);
    }
    __syncthreads();
    if (threadIdx.x < 4 && hc[threadIdx.x] > 0) atomicAdd(&g_cnt4[threadIdx.x], hc[threadIdx.x]);
}

// ---------------------------------------------------------------- main kernel
// grid (64, 16): CTA(x,q) computes tile pairs (x, (x+d)&63) for d=2q,2q+1
// (+d=32 for q==0, x<32). 8 warps = 4m x 2n, warp tile 32x64.
__global__ void __launch_bounds__(256, 1) main_kernel() {
    extern __shared__ char smraw[];
    char* smp = (char*)(((uintptr_t)smraw + 1023) & ~(uintptr_t)1023);
    const uint32_t sb = smem_u32(smp);

    const int tid = threadIdx.x;
    const int l = tid & 31, wid = tid >> 5;
    const int warp_m = wid >> 1, warp_n = wid & 1;
    const int x = blockIdx.x, q = blockIdx.y;
    const int ibase = x * 128;
    const int ntiles = 2 + ((q == 0 && x < 32) ? 1 : 0);

    load_tile(sb + OFF_AH, ibase, tid);
    cp_commit();
    {
        int tj0 = (x + 2 * q) & 63;
        load_tile(sb + OFF_B, tj0 * 128, tid);
        if (tid < 8) cp16(sb + OFF_CLS + tid * 16u, g_clsb + tj0 * 128 + tid * 16);
        cp_commit();
    }

    const uint32_t laneA = (uint32_t)((warp_m * 32 + (l & 15)) * (int)RSB + ((l >> 4) * 16));
    const uint32_t pAh = sb + OFF_AH + laneA;
    const uint32_t pAl = sb + OFF_AL + laneA;
    const uint32_t laneB = (uint32_t)((warp_n * 64 + (l & 15)) * (int)RSB + ((l >> 4) * 16));

    int pc[4], ncl[4];
    {
        int r0 = ibase + warp_m * 32 + (l >> 2);
#pragma unroll
        for (int ri = 0; ri < 4; ++ri) {
            int cr = g_cls[r0 + ri * 8];
            pc[ri] = cr ^ 1;
            ncl[ri] = cr ^ 2;
        }
    }

    float epos[4] = {0.f, 0.f, 0.f, 0.f};
    float eneg[4] = {0.f, 0.f, 0.f, 0.f};
    float lsum[4] = {0.f, 0.f, 0.f, 0.f};

    for (int t = 0; t < ntiles; ++t) {
        const int buf = t & 1;
        const int d = (t < 2) ? (2 * q + t) : 32;
        const int tj = (x + d) & 63;

        if (t + 1 < ntiles) {
            const int dn = (t + 1 < 2) ? (2 * q + t + 1) : 32;
            const int tjn = (x + dn) & 63;
            load_tile(sb + OFF_B + (uint32_t)(buf ^ 1) * 69632u, tjn * 128, tid);
            if (tid < 8)
                cp16(sb + OFF_CLS + (uint32_t)(buf ^ 1) * 128u + tid * 16u,
                     g_clsb + tjn * 128 + tid * 16);
            cp_commit();
            cp_wait1();
        } else {
            cp_wait0();
        }
        __syncthreads();

        const uint32_t pBh = sb + OFF_B + (uint32_t)buf * 69632u + laneB;
        const uint32_t pBl = pBh + 34816u;

        float acc[2][8][4];
#pragma unroll
        for (int mf = 0; mf < 2; ++mf)
#pragma unroll
            for (int nf = 0; nf < 8; ++nf)
#pragma unroll
                for (int c4 = 0; c4 < 4; ++c4) acc[mf][nf][c4] = 0.f;

#pragma unroll 1
        for (int ks = 0; ks < 8; ++ks) {
            const uint32_t ko = (uint32_t)ks * 32u;
            uint32_t aH[2][4], aL[2][4];
            ldsm4(aH[0], pAh + ko);
            ldsm4(aH[1], pAh + 16u * RSB + ko);
            ldsm4(aL[0], pAl + ko);
            ldsm4(aL[1], pAl + 16u * RSB + ko);
#pragma unroll
            for (int half = 0; half < 2; ++half) {
                uint32_t bh[2][4], bl[2][4];
                ldsm4(bh[0], pBh + (uint32_t)(half * 2) * 16u * RSB + ko);
                ldsm4(bh[1], pBh + (uint32_t)(half * 2 + 1) * 16u * RSB + ko);
                ldsm4(bl[0], pBl + (uint32_t)(half * 2) * 16u * RSB + ko);
                ldsm4(bl[1], pBl + (uint32_t)(half * 2 + 1) * 16u * RSB + ko);
                // split-major: same-acc dependency distance = 8
#pragma unroll
                for (int n2 = 0; n2 < 2; ++n2)
#pragma unroll
                    for (int qb = 0; qb < 2; ++qb)
#pragma unroll
                        for (int mf = 0; mf < 2; ++mf)
                            mma_bf16(acc[mf][(half * 2 + n2) * 2 + qb],
                                     aH[mf], bh[n2][qb], bh[n2][qb + 2]);
#pragma unroll
                for (int n2 = 0; n2 < 2; ++n2)
#pragma unroll
                    for (int qb = 0; qb < 2; ++qb)
#pragma unroll
                        for (int mf = 0; mf < 2; ++mf)
                            mma_bf16(acc[mf][(half * 2 + n2) * 2 + qb],
                                     aH[mf], bl[n2][qb], bl[n2][qb + 2]);
#pragma unroll
                for (int n2 = 0; n2 < 2; ++n2)
#pragma unroll
                    for (int qb = 0; qb < 2; ++qb)
#pragma unroll
                        for (int mf = 0; mf < 2; ++mf)
                            mma_bf16(acc[mf][(half * 2 + n2) * 2 + qb],
                                     aL[mf], bh[n2][qb], bh[n2][qb + 2]);
            }
        }

        // ---------------- epilogue: classify once, feed row + column sides
        float colE[8][2], colN[8][2], colL[8][2];
#pragma unroll
        for (int nf = 0; nf < 8; ++nf)
#pragma unroll
            for (int qc = 0; qc < 2; ++qc) {
                colE[nf][qc] = 0.f; colN[nf][qc] = 0.f; colL[nf][qc] = 0.f;
            }
        const float dc = (d != 0) ? 1.0f : 0.0f;
        const uint32_t clsb_s = sb + OFF_CLS + (uint32_t)buf * 128u +
                                (uint32_t)(warp_n * 64 + 2 * (l & 3));
#pragma unroll
        for (int nf = 0; nf < 8; ++nf) {
            unsigned short cw;
            asm volatile("ld.shared.u16 %0, [%1];" : "=h"(cw) : "r"(clsb_s + (uint32_t)nf * 8u));
            const int cj0 = cw & 0xff, cj1 = cw >> 8;
#pragma unroll
            for (int mf = 0; mf < 2; ++mf)
#pragma unroll
                for (int h = 0; h < 2; ++h) {
                    const int ri = mf * 2 + h;
                    float v0 = acc[mf][nf][h * 2 + 0];
                    float v1 = acc[mf][nf][h * 2 + 1];
                    float e0 = ex2f(v0), e1 = ex2f(v1);
                    if (cj0 == pc[ri]) {
                        epos[ri] += e0; lsum[ri] += v0;
                        colE[nf][0] += dc * e0; colL[nf][0] += dc * v0;
                    } else if (cj0 == ncl[ri]) {
                        eneg[ri] += e0; colN[nf][0] += dc * e0;
                    }
                    if (cj1 == pc[ri]) {
                        epos[ri] += e1; lsum[ri] += v1;
                        colE[nf][1] += dc * e1; colL[nf][1] += dc * v1;
                    } else if (cj1 == ncl[ri]) {
                        eneg[ri] += e1; colN[nf][1] += dc * e1;
                    }
                }
        }

        // ---------------- column-side flush (off-diagonal tiles only)
        if (d != 0) {
#pragma unroll
            for (int nf = 0; nf < 8; ++nf)
#pragma unroll
                for (int qc = 0; qc < 2; ++qc) {
#pragma unroll
                    for (int s = 4; s <= 16; s <<= 1) {
                        colE[nf][qc] += __shfl_xor_sync(0xffffffffu, colE[nf][qc], s);
                        colN[nf][qc] += __shfl_xor_sync(0xffffffffu, colN[nf][qc], s);
                        colL[nf][qc] += __shfl_xor_sync(0xffffffffu, colL[nf][qc], s);
                    }
                }
            if ((l >> 2) == 0) {
                float* red = (float*)(smp + OFF_RED);
#pragma unroll
                for (int nf = 0; nf < 8; ++nf)
#pragma unroll
                    for (int qc = 0; qc < 2; ++qc) {
                        int col = warp_n * 64 + nf * 8 + 2 * l + qc;
                        int base = (warp_m * 128 + col) * 3;
                        red[base + 0] = colE[nf][qc];
                        red[base + 1] = colN[nf][qc];
                        red[base + 2] = colL[nf][qc];
                    }
            }
        }
        __syncthreads();
        if (d != 0 && tid < 128) {
            const float* red = (const float*)(smp + OFF_RED);
            float E = 0.f, N = 0.f, L = 0.f;
#pragma unroll
            for (int wm = 0; wm < 4; ++wm) {
                int base = (wm * 128 + tid) * 3;
                E += red[base]; N += red[base + 1]; L += red[base + 2];
            }
            g_cpart[d - 1][tj * 128 + tid] = make_float4(E, N, L, 0.f);
        }
        __syncthreads();
    }

    // ---------------- row-side flush
#pragma unroll
    for (int ri = 0; ri < 4; ++ri) {
        epos[ri] += __shfl_xor_sync(0xffffffffu, epos[ri], 1);
        epos[ri] += __shfl_xor_sync(0xffffffffu, epos[ri], 2);
        eneg[ri] += __shfl_xor_sync(0xffffffffu, eneg[ri], 1);
        eneg[ri] += __shfl_xor_sync(0xffffffffu, eneg[ri], 2);
        lsum[ri] += __shfl_xor_sync(0xffffffffu, lsum[ri], 1);
        lsum[ri] += __shfl_xor_sync(0xffffffffu, lsum[ri], 2);
    }
    float* red = (float*)(smp + OFF_RED);   // [128][2][3]
    if ((l & 3) == 0) {
#pragma unroll
        for (int ri = 0; ri < 4; ++ri) {
            int row = warp_m * 32 + (l >> 2) + ri * 8;
            red[(row * 2 + warp_n) * 3 + 0] = epos[ri];
            red[(row * 2 + warp_n) * 3 + 1] = eneg[ri];
            red[(row * 2 + warp_n) * 3 + 2] = lsum[ri];
        }
    }
    __syncthreads();
    if (tid < 128) {
        float Ep = red[(tid * 2) * 3 + 0] + red[(tid * 2 + 1) * 3 + 0];
        float En = red[(tid * 2) * 3 + 1] + red[(tid * 2 + 1) * 3 + 1];
        float Ls = red[(tid * 2) * 3 + 2] + red[(tid * 2 + 1) * 3 + 2];
        g_rpart[q][ibase + tid] = make_float4(Ep, En, Ls, 0.f);
    }
}

// ---------------------------------------------------------------- per-row values
__global__ void rowval_kernel() {
    int i = blockIdx.x * 256 + threadIdx.x;
    float Ep = 0.f, En = 0.f, Ls = 0.f;
#pragma unroll
    for (int qq = 0; qq < 16; ++qq) {
        float4 p = g_rpart[qq][i];
        Ep += p.x; En += p.y; Ls += p.z;
    }
#pragma unroll
    for (int s = 0; s < 31; ++s) {
        float4 p = g_cpart[s][i];
        Ep += p.x; En += p.y; Ls += p.z;
    }
    if (i >= 4096) {   // d=32 slice only covers rows [4096, 8192)
        float4 p = g_cpart[31][i];
        Ep += p.x; En += p.y; Ls += p.z;
    }
    int ci = g_cls[i];
    int pcnt = g_cnt4[ci ^ 1];
    int ncnt = g_cnt4[ci ^ 2];
    float val = 0.f;
    if (pcnt > 0 && ncnt > 0)
        val = (Ls * 0.6931471805599453f - (float)pcnt * logf(Ep + En)) / (float)pcnt;
    g_rowval[i] = val;
}

// ---------------------------------------------------------------- final sum
__global__ void sum_kernel(float* __restrict__ out) {
    __shared__ float s[256];
    float acc = 0.f;
    for (int i = threadIdx.x; i < B_SZ; i += 256) acc += g_rowval[i];
    s[threadIdx.x] = acc;
    __syncthreads();
    for (int o = 128; o; o >>= 1) {
        if (threadIdx.x < o) s[threadIdx.x] += s[threadIdx.x + o];
        __syncthreads();
    }
    if (threadIdx.x == 0) out[0] = -s[0] / (float)B_SZ;
}

// ---------------------------------------------------------------- launch
extern "C" void kernel_launch(void* const* d_in, const int* in_sizes, int n_in,
                              void* d_out, int out_size) {
    const float* F = (const float*)d_in[0];
    const void* dix = d_in[1];
    const void* tt  = d_in[2];
    const void* tp  = d_in[3];
    float* out = (float*)d_out;

    detect_kernel<<<1, 256>>>((const long long*)dix);
    prep_kernel<<<(B_SZ * 32) / 256, 256>>>(F, dix, tt, tp);

    cudaFuncSetAttribute(main_kernel, cudaFuncAttributeMaxDynamicSharedMemorySize, SMEM_BYTES);
    main_kernel<<<dim3(64, 16), 256, SMEM_BYTES>>>();

    rowval_kernel<<<32, 256>>>();
    sum_kernel<<<1, 256>>>(out);
}

// round 5
// speedup vs baseline: 4.2013x; 1.1378x over previous
#include <cuda_runtime.h>
#include <cuda_bf16.h>
#include <cstdint>

// ContrastiveLoss B=8192 D=128 T=0.1, classes c=2*tt+tp in {0..3}
// Symmetric-pair HMMA bf16 3-split. Round 5: 128 CTAs x 512 threads
// (16 warps, 4 warps/SMSP), 16-17 tiles per CTA, warp tile 32x32.

#define B_SZ 8192
#define RSB  272u            // smem row stride bytes (128 bf16 + pad)
#define OFF_AH 0u
#define OFF_AL 34816u        // 128*272
#define OFF_B  69632u        // + buf*69632 ; hi at +0, lo at +34816
#define OFF_CLS 208896u      // + buf*128
#define OFF_RED 209152u      // 1536 floats = 6144 B
#define SMEM_BYTES (209152 + 6144 + 1024)

// ---------------------------------------------------------------- globals
__device__ __align__(256) __nv_bfloat16 g_hi[B_SZ * 128];
__device__ __align__(256) __nv_bfloat16 g_lo[B_SZ * 128];
__device__ int           g_cls[B_SZ];
__device__ __align__(256) unsigned char g_clsb[B_SZ];
__device__ int           g_cnt4[4];
__device__ float4        g_rpart[2][B_SZ];    // row-side partials per q
__device__ float4        g_cpart[32][B_SZ];   // col-side partials per (d-1)
__device__ float         g_rowval[B_SZ];
__device__ int           g_is64;

// ---------------------------------------------------------------- helpers
__device__ __forceinline__ uint32_t smem_u32(const void* p) {
    uint32_t a;
    asm("{ .reg .u64 t; cvta.to.shared.u64 t, %1; cvt.u32.u64 %0, t; }" : "=r"(a) : "l"(p));
    return a;
}
__device__ __forceinline__ void cp16(uint32_t dst, const void* src) {
    asm volatile("cp.async.cg.shared.global [%0], [%1], 16;" :: "r"(dst), "l"(src) : "memory");
}
__device__ __forceinline__ void cp_commit() {
    asm volatile("cp.async.commit_group;" ::: "memory");
}
__device__ __forceinline__ void cp_wait0() {
    asm volatile("cp.async.wait_group 0;" ::: "memory");
}
__device__ __forceinline__ void cp_wait1() {
    asm volatile("cp.async.wait_group 1;" ::: "memory");
}
__device__ __forceinline__ void ldsm4(uint32_t* r, uint32_t addr) {
    asm volatile("ldmatrix.sync.aligned.m8n8.x4.shared.b16 {%0,%1,%2,%3}, [%4];"
                 : "=r"(r[0]), "=r"(r[1]), "=r"(r[2]), "=r"(r[3]) : "r"(addr));
}
__device__ __forceinline__ void mma_bf16(float* c, const uint32_t* a, uint32_t b0, uint32_t b1) {
    asm volatile(
        "mma.sync.aligned.m16n8k16.row.col.f32.bf16.bf16.f32 "
        "{%0,%1,%2,%3}, {%4,%5,%6,%7}, {%8,%9}, {%0,%1,%2,%3};"
        : "+f"(c[0]), "+f"(c[1]), "+f"(c[2]), "+f"(c[3])
        : "r"(a[0]), "r"(a[1]), "r"(a[2]), "r"(a[3]), "r"(b0), "r"(b1));
}
__device__ __forceinline__ float ex2f(float v) {
    float e;
    asm("ex2.approx.ftz.f32 %0, %1;" : "=f"(e) : "f"(v));
    return e;
}

// async load one hi+lo tile pair (128 rows x 256B) into padded smem rows
__device__ __forceinline__ void load_tile(uint32_t sdst_h, int rowbase, int tid) {
#pragma unroll
    for (int i = 0; i < 4; ++i) {
        int idx = tid + i * 512;
        int r = idx >> 4, c = idx & 15;
        uint32_t dst = sdst_h + (uint32_t)r * RSB + (uint32_t)c * 16u;
        cp16(dst, g_hi + (size_t)(rowbase + r) * 128 + c * 8);
        cp16(dst + 34816u, g_lo + (size_t)(rowbase + r) * 128 + c * 8);
    }
}

// ---------------------------------------------------------------- detect + init
__global__ void detect_kernel(const long long* __restrict__ dix64) {
    __shared__ int bad;
    if (threadIdx.x == 0) bad = 0;
    __syncthreads();
    int local = 0;
    for (int i = threadIdx.x; i < 4096; i += blockDim.x) {
        long long v = dix64[i];
        if (v < 0 || v >= 100000) local = 1;
    }
    if (local) atomicOr(&bad, 1);
    __syncthreads();
    if (threadIdx.x == 0) g_is64 = (bad == 0) ? 1 : 0;
    if (threadIdx.x < 4) g_cnt4[threadIdx.x] = 0;
}

// ---------------------------------------------------------------- prep (+hist)
__global__ void prep_kernel(const float* __restrict__ F,
                            const void* __restrict__ data_ix,
                            const void* __restrict__ tt,
                            const void* __restrict__ tp) {
    __shared__ int hc[4];
    if (threadIdx.x < 4) hc[threadIdx.x] = 0;
    __syncthreads();
    int warp = (blockIdx.x * blockDim.x + threadIdx.x) >> 5;
    int lane = threadIdx.x & 31;
    const float* row = F + (size_t)warp * 128;
    float v0 = row[lane], v1 = row[lane + 32], v2 = row[lane + 64], v3 = row[lane + 96];
    float ss = v0 * v0 + v1 * v1 + v2 * v2 + v3 * v3;
#pragma unroll
    for (int o = 16; o; o >>= 1) ss += __shfl_xor_sync(0xffffffffu, ss, o);
    float scale = sqrtf(14.4269504088896f) / sqrtf(ss);   // sqrt(log2e / T)
    float g[4] = {v0 * scale, v1 * scale, v2 * scale, v3 * scale};
#pragma unroll
    for (int qq = 0; qq < 4; ++qq) {
        __nv_bfloat16 h = __float2bfloat16(g[qq]);
        __nv_bfloat16 lo = __float2bfloat16(g[qq] - __bfloat162float(h));
        g_hi[(size_t)warp * 128 + lane + qq * 32] = h;
        g_lo[(size_t)warp * 128 + lane + qq * 32] = lo;
    }
    if (lane == 0) {
        long long ix;
        int t, p;
        if (g_is64) {
            ix = ((const long long*)data_ix)[warp];
            t = (int)((const long long*)tt)[ix];
            p = (int)((const long long*)tp)[ix];
        } else {
            ix = (long long)((const int*)data_ix)[warp];
            t = ((const int*)tt)[ix];
            p = ((const int*)tp)[ix];
        }
        int cls = t * 2 + p;
        g_cls[warp] = cls;
        g_clsb[warp] = (unsigned char)cls;
        atomicAdd(&hc[cls], 1);
    }
    __syncthreads();
    if (threadIdx.x < 4 && hc[threadIdx.x] > 0) atomicAdd(&g_cnt4[threadIdx.x], hc[threadIdx.x]);
}

// ---------------------------------------------------------------- main kernel
// grid (64, 2): CTA(x,q) computes tile pairs (x, (x+d)&63) for d=16q+t, t<16
// (+d=32 for q==0, x<32). 16 warps = 4m x 4n, warp tile 32x32.
__global__ void __launch_bounds__(512, 1) main_kernel() {
    extern __shared__ char smraw[];
    char* smp = (char*)(((uintptr_t)smraw + 1023) & ~(uintptr_t)1023);
    const uint32_t sb = smem_u32(smp);

    const int tid = threadIdx.x;
    const int l = tid & 31, wid = tid >> 5;
    const int warp_m = wid >> 2, warp_n = wid & 3;
    const int x = blockIdx.x, q = blockIdx.y;
    const int ibase = x * 128;
    const int ntiles = 16 + ((q == 0 && x < 32) ? 1 : 0);

    load_tile(sb + OFF_AH, ibase, tid);
    cp_commit();
    {
        int tj0 = (x + 16 * q) & 63;
        load_tile(sb + OFF_B, tj0 * 128, tid);
        if (tid < 8) cp16(sb + OFF_CLS + tid * 16u, g_clsb + tj0 * 128 + tid * 16);
        cp_commit();
    }

    const uint32_t laneA = (uint32_t)((warp_m * 32 + (l & 15)) * (int)RSB + ((l >> 4) * 16));
    const uint32_t pAh = sb + OFF_AH + laneA;
    const uint32_t pAl = sb + OFF_AL + laneA;
    const uint32_t laneB = (uint32_t)((warp_n * 32 + (l & 15)) * (int)RSB + ((l >> 4) * 16));

    int pc[4], ncl[4];
    {
        int r0 = ibase + warp_m * 32 + (l >> 2);
#pragma unroll
        for (int ri = 0; ri < 4; ++ri) {
            int cr = g_cls[r0 + ri * 8];
            pc[ri] = cr ^ 1;
            ncl[ri] = cr ^ 2;
        }
    }

    float epos[4] = {0.f, 0.f, 0.f, 0.f};
    float eneg[4] = {0.f, 0.f, 0.f, 0.f};
    float lsum[4] = {0.f, 0.f, 0.f, 0.f};

    for (int t = 0; t < ntiles; ++t) {
        const int buf = t & 1;
        const int d = (t < 16) ? (16 * q + t) : 32;
        const int tj = (x + d) & 63;

        if (t + 1 < ntiles) {
            const int dn = (t + 1 < 16) ? (16 * q + t + 1) : 32;
            const int tjn = (x + dn) & 63;
            load_tile(sb + OFF_B + (uint32_t)(buf ^ 1) * 69632u, tjn * 128, tid);
            if (tid < 8)
                cp16(sb + OFF_CLS + (uint32_t)(buf ^ 1) * 128u + tid * 16u,
                     g_clsb + tjn * 128 + tid * 16);
            cp_commit();
            cp_wait1();
        } else {
            cp_wait0();
        }
        __syncthreads();

        const uint32_t pBh = sb + OFF_B + (uint32_t)buf * 69632u + laneB;
        const uint32_t pBl = pBh + 34816u;

        float acc[2][4][4];
#pragma unroll
        for (int mf = 0; mf < 2; ++mf)
#pragma unroll
            for (int nf = 0; nf < 4; ++nf)
#pragma unroll
                for (int c4 = 0; c4 < 4; ++c4) acc[mf][nf][c4] = 0.f;

#pragma unroll 1
        for (int ks = 0; ks < 8; ++ks) {
            const uint32_t ko = (uint32_t)ks * 32u;
            uint32_t aH[2][4], aL[2][4], bh[2][4], bl[2][4];
            ldsm4(aH[0], pAh + ko);
            ldsm4(aH[1], pAh + 16u * RSB + ko);
            ldsm4(aL[0], pAl + ko);
            ldsm4(aL[1], pAl + 16u * RSB + ko);
            ldsm4(bh[0], pBh + ko);
            ldsm4(bh[1], pBh + 16u * RSB + ko);
            ldsm4(bl[0], pBl + ko);
            ldsm4(bl[1], pBl + 16u * RSB + ko);
            // split-major: same-acc dependency distance = 8
#pragma unroll
            for (int n2 = 0; n2 < 2; ++n2)
#pragma unroll
                for (int qb = 0; qb < 2; ++qb)
#pragma unroll
                    for (int mf = 0; mf < 2; ++mf)
                        mma_bf16(acc[mf][n2 * 2 + qb], aH[mf], bh[n2][qb], bh[n2][qb + 2]);
#pragma unroll
            for (int n2 = 0; n2 < 2; ++n2)
#pragma unroll
                for (int qb = 0; qb < 2; ++qb)
#pragma unroll
                    for (int mf = 0; mf < 2; ++mf)
                        mma_bf16(acc[mf][n2 * 2 + qb], aH[mf], bl[n2][qb], bl[n2][qb + 2]);
#pragma unroll
            for (int n2 = 0; n2 < 2; ++n2)
#pragma unroll
                for (int qb = 0; qb < 2; ++qb)
#pragma unroll
                    for (int mf = 0; mf < 2; ++mf)
                        mma_bf16(acc[mf][n2 * 2 + qb], aL[mf], bh[n2][qb], bh[n2][qb + 2]);
        }

        // ---------------- epilogue: classify once, feed row + column sides
        const float dc = (d != 0) ? 1.0f : 0.0f;
        const uint32_t clsb_s = sb + OFF_CLS + (uint32_t)buf * 128u +
                                (uint32_t)(warp_n * 32 + 2 * (l & 3));
        float* red = (float*)(smp + OFF_RED);
#pragma unroll
        for (int nf = 0; nf < 4; ++nf) {
            unsigned short cw;
            asm volatile("ld.shared.u16 %0, [%1];" : "=h"(cw) : "r"(clsb_s + (uint32_t)nf * 8u));
            const int cj0 = cw & 0xff, cj1 = cw >> 8;
            float cE0 = 0.f, cE1 = 0.f, cN0 = 0.f, cN1 = 0.f, cL0 = 0.f, cL1 = 0.f;
#pragma unroll
            for (int mf = 0; mf < 2; ++mf)
#pragma unroll
                for (int h = 0; h < 2; ++h) {
                    const int ri = mf * 2 + h;
                    float v0 = acc[mf][nf][h * 2 + 0];
                    float v1 = acc[mf][nf][h * 2 + 1];
                    float e0 = ex2f(v0), e1 = ex2f(v1);
                    if (cj0 == pc[ri]) { epos[ri] += e0; lsum[ri] += v0;
                                         cE0 += dc * e0; cL0 += dc * v0; }
                    else if (cj0 == ncl[ri]) { eneg[ri] += e0; cN0 += dc * e0; }
                    if (cj1 == pc[ri]) { epos[ri] += e1; lsum[ri] += v1;
                                         cE1 += dc * e1; cL1 += dc * v1; }
                    else if (cj1 == ncl[ri]) { eneg[ri] += e1; cN1 += dc * e1; }
                }
            if (d != 0) {
#pragma unroll
                for (int s = 4; s <= 16; s <<= 1) {
                    cE0 += __shfl_xor_sync(0xffffffffu, cE0, s);
                    cE1 += __shfl_xor_sync(0xffffffffu, cE1, s);
                    cN0 += __shfl_xor_sync(0xffffffffu, cN0, s);
                    cN1 += __shfl_xor_sync(0xffffffffu, cN1, s);
                    cL0 += __shfl_xor_sync(0xffffffffu, cL0, s);
                    cL1 += __shfl_xor_sync(0xffffffffu, cL1, s);
                }
                if ((l >> 2) == 0) {
                    int col = warp_n * 32 + nf * 8 + 2 * l;   // l = l&3 here
                    int base = (warp_m * 128 + col) * 3;
                    red[base + 0] = cE0; red[base + 1] = cN0; red[base + 2] = cL0;
                    red[base + 3] = cE1; red[base + 4] = cN1; red[base + 5] = cL1;
                }
            }
        }
        __syncthreads();
        if (d != 0 && tid < 128) {
            float E = 0.f, N = 0.f, L = 0.f;
#pragma unroll
            for (int wm = 0; wm < 4; ++wm) {
                int base = (wm * 128 + tid) * 3;
                E += red[base]; N += red[base + 1]; L += red[base + 2];
            }
            g_cpart[d - 1][tj * 128 + tid] = make_float4(E, N, L, 0.f);
        }
        __syncthreads();
    }

    // ---------------- row-side flush
#pragma unroll
    for (int ri = 0; ri < 4; ++ri) {
        epos[ri] += __shfl_xor_sync(0xffffffffu, epos[ri], 1);
        epos[ri] += __shfl_xor_sync(0xffffffffu, epos[ri], 2);
        eneg[ri] += __shfl_xor_sync(0xffffffffu, eneg[ri], 1);
        eneg[ri] += __shfl_xor_sync(0xffffffffu, eneg[ri], 2);
        lsum[ri] += __shfl_xor_sync(0xffffffffu, lsum[ri], 1);
        lsum[ri] += __shfl_xor_sync(0xffffffffu, lsum[ri], 2);
    }
    float* red = (float*)(smp + OFF_RED);   // [128 rows][4 warp_n][3]
    if ((l & 3) == 0) {
#pragma unroll
        for (int ri = 0; ri < 4; ++ri) {
            int row = warp_m * 32 + (l >> 2) + ri * 8;
            red[(row * 4 + warp_n) * 3 + 0] = epos[ri];
            red[(row * 4 + warp_n) * 3 + 1] = eneg[ri];
            red[(row * 4 + warp_n) * 3 + 2] = lsum[ri];
        }
    }
    __syncthreads();
    if (tid < 128) {
        float Ep = 0.f, En = 0.f, Ls = 0.f;
#pragma unroll
        for (int wn = 0; wn < 4; ++wn) {
            Ep += red[(tid * 4 + wn) * 3 + 0];
            En += red[(tid * 4 + wn) * 3 + 1];
            Ls += red[(tid * 4 + wn) * 3 + 2];
        }
        g_rpart[q][ibase + tid] = make_float4(Ep, En, Ls, 0.f);
    }
}

// ---------------------------------------------------------------- per-row values
__global__ void rowval_kernel() {
    int i = blockIdx.x * 256 + threadIdx.x;
    float Ep = 0.f, En = 0.f, Ls = 0.f;
#pragma unroll
    for (int qq = 0; qq < 2; ++qq) {
        float4 p = g_rpart[qq][i];
        Ep += p.x; En += p.y; Ls += p.z;
    }
#pragma unroll
    for (int s = 0; s < 31; ++s) {
        float4 p = g_cpart[s][i];
        Ep += p.x; En += p.y; Ls += p.z;
    }
    if (i >= 4096) {   // d=32 col slice only covers rows [4096, 8192)
        float4 p = g_cpart[31][i];
        Ep += p.x; En += p.y; Ls += p.z;
    }
    int ci = g_cls[i];
    int pcnt = g_cnt4[ci ^ 1];
    int ncnt = g_cnt4[ci ^ 2];
    float val = 0.f;
    if (pcnt > 0 && ncnt > 0)
        val = (Ls * 0.6931471805599453f - (float)pcnt * logf(Ep + En)) / (float)pcnt;
    g_rowval[i] = val;
}

// ---------------------------------------------------------------- final sum
__global__ void sum_kernel(float* __restrict__ out) {
    __shared__ float s[256];
    float acc = 0.f;
    for (int i = threadIdx.x; i < B_SZ; i += 256) acc += g_rowval[i];
    s[threadIdx.x] = acc;
    __syncthreads();
    for (int o = 128; o; o >>= 1) {
        if (threadIdx.x < o) s[threadIdx.x] += s[threadIdx.x + o];
        __syncthreads();
    }
    if (threadIdx.x == 0) out[0] = -s[0] / (float)B_SZ;
}

// ---------------------------------------------------------------- launch
extern "C" void kernel_launch(void* const* d_in, const int* in_sizes, int n_in,
                              void* d_out, int out_size) {
    const float* F = (const float*)d_in[0];
    const void* dix = d_in[1];
    const void* tt  = d_in[2];
    const void* tp  = d_in[3];
    float* out = (float*)d_out;

    detect_kernel<<<1, 256>>>((const long long*)dix);
    prep_kernel<<<(B_SZ * 32) / 256, 256>>>(F, dix, tt, tp);

    cudaFuncSetAttribute(main_kernel, cudaFuncAttributeMaxDynamicSharedMemorySize, SMEM_BYTES);
    main_kernel<<<dim3(64, 2), 512, SMEM_BYTES>>>();

    rowval_kernel<<<32, 256>>>();
    sum_kernel<<<1, 256>>>(out);
}

// round 10
// speedup vs baseline: 4.3873x; 1.0443x over previous
#include <cuda_runtime.h>
#include <cuda_bf16.h>
#include <cstdint>

// ContrastiveLoss B=8192 D=128 T=0.1, classes c=2*tt+tp in {0..3}
// Round 10: R9 + FIX of the real R6-R9 bug: load_tile64 only filled 128 of the
// 256 bytes per row (K=64..127 never loaded -> ldsm read garbage -> NaN).
// Design: symmetric pairs, 64-row CTAs, grid (128,2) x 256 thr, 2 CTAs/SM.

#define B_SZ 8192
#define RSB  272u                 // smem row stride bytes (256 data + 16 pad)
#define ATILE 17408u              // 64 rows * 272
#define OFF_B   34816u            // + buf*34816 ; hi +0, lo +17408
#define OFF_CLS 104448u           // + buf*64
#define OFF_RED 104576u           // 3072 B scratch
#define SMEM_BYTES (104576 + 3072 + 1024)

// ---------------------------------------------------------------- globals
__device__ __align__(256) __nv_bfloat16 g_hi[B_SZ * 128];
__device__ __align__(256) __nv_bfloat16 g_lo[B_SZ * 128];
__device__ int           g_cls[B_SZ];
__device__ __align__(256) unsigned char g_clsb[B_SZ];
__device__ int           g_cnt4[4];
__device__ float4        g_rpart[2][B_SZ];    // row-side partials per q
__device__ float4        g_cpart[64][B_SZ];   // col-side partials per (d-1), d=1..64
__device__ float         g_rowval[B_SZ];
__device__ int           g_is64;

// ---------------------------------------------------------------- helpers
__device__ __forceinline__ uint32_t smem_u32(const void* p) {
    uint32_t a;
    asm("{ .reg .u64 t; cvta.to.shared.u64 t, %1; cvt.u32.u64 %0, t; }" : "=r"(a) : "l"(p));
    return a;
}
__device__ __forceinline__ void cp16(uint32_t dst, const void* src) {
    asm volatile("cp.async.cg.shared.global [%0], [%1], 16;" :: "r"(dst), "l"(src) : "memory");
}
__device__ __forceinline__ void cp_commit() {
    asm volatile("cp.async.commit_group;" ::: "memory");
}
__device__ __forceinline__ void cp_wait0() {
    asm volatile("cp.async.wait_group 0;" ::: "memory");
}
__device__ __forceinline__ void cp_wait1() {
    asm volatile("cp.async.wait_group 1;" ::: "memory");
}
__device__ __forceinline__ void ldsm4(uint32_t* r, uint32_t addr) {
    asm volatile("ldmatrix.sync.aligned.m8n8.x4.shared.b16 {%0,%1,%2,%3}, [%4];"
                 : "=r"(r[0]), "=r"(r[1]), "=r"(r[2]), "=r"(r[3]) : "r"(addr));
}
__device__ __forceinline__ void mma_bf16(float* c, const uint32_t* a, uint32_t b0, uint32_t b1) {
    asm volatile(
        "mma.sync.aligned.m16n8k16.row.col.f32.bf16.bf16.f32 "
        "{%0,%1,%2,%3}, {%4,%5,%6,%7}, {%8,%9}, {%0,%1,%2,%3};"
        : "+f"(c[0]), "+f"(c[1]), "+f"(c[2]), "+f"(c[3])
        : "r"(a[0]), "r"(a[1]), "r"(a[2]), "r"(a[3]), "r"(b0), "r"(b1));
}
__device__ __forceinline__ float ex2f(float v) {
    float e;
    asm("ex2.approx.ftz.f32 %0, %1;" : "=f"(e) : "f"(v));
    return e;
}

// async load one hi+lo 64-row tile into padded smem rows.
// FIX(R10): rows are 128 bf16 = 256 BYTES. 64 rows -> 1024 cp16 per buffer
// (4 iterations x 256 threads), r = idx>>4, c = idx&15. R6-R9 used idx>>3 /
// idx&7, which filled only the first 128 bytes of each row (K 0..63) and left
// K 64..127 as garbage -> NaN.
__device__ __forceinline__ void load_tile64(uint32_t sdst_h, int rowbase, int tid) {
#pragma unroll
    for (int i = 0; i < 4; ++i) {
        int idx = tid + i * 256;             // 0..1023
        int r = idx >> 4, c = idx & 15;      // r: 0..63, c: 0..15 (16B chunks)
        uint32_t dst = sdst_h + (uint32_t)r * RSB + (uint32_t)c * 16u;
        cp16(dst, g_hi + (size_t)(rowbase + r) * 128 + c * 8);
        cp16(dst + ATILE, g_lo + (size_t)(rowbase + r) * 128 + c * 8);
    }
}

// ---------------------------------------------------------------- zero partials
// g_cpart[63] rows <4096 are read by rowval but never written by main; module
// globals are not reliably zero -> clear all partial buffers every launch.
__global__ void zero_kernel() {
    size_t n = (size_t)64 * B_SZ + 2 * B_SZ;   // cpart + rpart, in float4 units
    float4* base = &g_cpart[0][0];
    float4* rp = &g_rpart[0][0];
    size_t idx = (size_t)blockIdx.x * blockDim.x + threadIdx.x;
    size_t stride = (size_t)gridDim.x * blockDim.x;
    for (size_t i = idx; i < n; i += stride) {
        if (i < (size_t)64 * B_SZ) base[i] = make_float4(0.f, 0.f, 0.f, 0.f);
        else rp[i - (size_t)64 * B_SZ] = make_float4(0.f, 0.f, 0.f, 0.f);
    }
}

// ---------------------------------------------------------------- detect + init
__global__ void detect_kernel(const long long* __restrict__ dix64) {
    __shared__ int bad;
    if (threadIdx.x == 0) bad = 0;
    __syncthreads();
    int local = 0;
    for (int i = threadIdx.x; i < 4096; i += blockDim.x) {
        long long v = dix64[i];
        if (v < 0 || v >= 100000) local = 1;
    }
    if (local) atomicOr(&bad, 1);
    __syncthreads();
    if (threadIdx.x == 0) g_is64 = (bad == 0) ? 1 : 0;
    if (threadIdx.x < 4) g_cnt4[threadIdx.x] = 0;
}

// ---------------------------------------------------------------- prep (+hist)
__global__ void prep_kernel(const float* __restrict__ F,
                            const void* __restrict__ data_ix,
                            const void* __restrict__ tt,
                            const void* __restrict__ tp) {
    __shared__ int hc[4];
    if (threadIdx.x < 4) hc[threadIdx.x] = 0;
    __syncthreads();
    int warp = (blockIdx.x * blockDim.x + threadIdx.x) >> 5;
    int lane = threadIdx.x & 31;
    const float* row = F + (size_t)warp * 128;
    float v0 = row[lane], v1 = row[lane + 32], v2 = row[lane + 64], v3 = row[lane + 96];
    float ss = v0 * v0 + v1 * v1 + v2 * v2 + v3 * v3;
#pragma unroll
    for (int o = 16; o; o >>= 1) ss += __shfl_xor_sync(0xffffffffu, ss, o);
    float scale = sqrtf(14.4269504088896f) / sqrtf(ss);   // sqrt(log2e / T)
    float g[4] = {v0 * scale, v1 * scale, v2 * scale, v3 * scale};
#pragma unroll
    for (int qq = 0; qq < 4; ++qq) {
        __nv_bfloat16 h = __float2bfloat16(g[qq]);
        __nv_bfloat16 lo = __float2bfloat16(g[qq] - __bfloat162float(h));
        g_hi[(size_t)warp * 128 + lane + qq * 32] = h;
        g_lo[(size_t)warp * 128 + lane + qq * 32] = lo;
    }
    if (lane == 0) {
        long long ix;
        int t, p;
        if (g_is64) {
            ix = ((const long long*)data_ix)[warp];
            t = (int)((const long long*)tt)[ix];
            p = (int)((const long long*)tp)[ix];
        } else {
            ix = (long long)((const int*)data_ix)[warp];
            t = ((const int*)tt)[ix];
            p = ((const int*)tp)[ix];
        }
        int cls = t * 2 + p;
        g_cls[warp] = cls;
        g_clsb[warp] = (unsigned char)cls;
        atomicAdd(&hc[cls], 1);
    }
    __syncthreads();
    if (threadIdx.x < 4 && hc[threadIdx.x] > 0) atomicAdd(&g_cnt4[threadIdx.x], hc[threadIdx.x]);
}

// ---------------------------------------------------------------- main kernel
// grid (128, 2), 256 thr = 8 warps (2m x 4n), warp tile 32x16.
// CTA (x,q): A = block x (loaded once), jobs d = 32q+t (t<32) + d=64 for q==0 && x<64.
__global__ void __launch_bounds__(256, 2) main_kernel() {
    extern __shared__ char smraw[];
    char* smp = (char*)(((uintptr_t)smraw + 1023) & ~(uintptr_t)1023);
    const uint32_t sb = smem_u32(smp);
    float* red = (float*)(smp + OFF_RED);

    const int tid = threadIdx.x;
    const int l = tid & 31, wid = tid >> 5;
    const int warp_m = wid >> 2, warp_n = wid & 3;
    const int x = blockIdx.x, q = blockIdx.y;
    const int njobs = 32 + ((q == 0 && x < 64) ? 1 : 0);

    // A tile (persistent, loaded once) then B tile for job 0
    load_tile64(sb + 0u, x * 64, tid);
    cp_commit();
    {
        int d0 = 32 * q;                       // t = 0
        int tj0 = (x + d0) & 127;
        load_tile64(sb + OFF_B, tj0 * 64, tid);
        if (tid < 4) cp16(sb + OFF_CLS + tid * 16u, g_clsb + tj0 * 64 + tid * 16);
        cp_commit();
    }

    const uint32_t laneA = (uint32_t)((warp_m * 32 + (l & 15)) * (int)RSB + ((l >> 4) * 16));
    const uint32_t pAh = sb + laneA;
    const uint32_t pAl = sb + ATILE + laneA;
    const uint32_t laneB = (uint32_t)((warp_n * 16 + (l & 15)) * (int)RSB + ((l >> 4) * 16));

    int pc[4], ncl[4];
#pragma unroll
    for (int ri = 0; ri < 4; ++ri) {
        int row = warp_m * 32 + (ri >> 1) * 16 + (ri & 1) * 8 + (l >> 2);
        int cr = g_cls[x * 64 + row];
        pc[ri] = cr ^ 1;
        ncl[ri] = cr ^ 2;
    }

    float epos[4] = {0.f, 0.f, 0.f, 0.f};
    float eneg[4] = {0.f, 0.f, 0.f, 0.f};
    float lsum[4] = {0.f, 0.f, 0.f, 0.f};

    for (int t = 0; t < njobs; ++t) {
        const int buf = t & 1;
        const int d = (t < 32) ? (32 * q + t) : 64;
        const int tj = (x + d) & 127;

        if (t + 1 < njobs) {
            const int dn = (t + 1 < 32) ? (32 * q + t + 1) : 64;
            const int tjn = (x + dn) & 127;
            load_tile64(sb + OFF_B + (uint32_t)(buf ^ 1) * 34816u, tjn * 64, tid);
            if (tid < 4)
                cp16(sb + OFF_CLS + (uint32_t)(buf ^ 1) * 64u + tid * 16u,
                     g_clsb + tjn * 64 + tid * 16);
            cp_commit();
            cp_wait1();
        } else {
            cp_wait0();
        }
        __syncthreads();

        // ---------------- MMA: 64x64 tile, K=128, 3 splits
        const uint32_t pBh = sb + OFF_B + (uint32_t)buf * 34816u + laneB;
        const uint32_t pBl = pBh + ATILE;

        float acc[2][2][4];
#pragma unroll
        for (int mf = 0; mf < 2; ++mf)
#pragma unroll
            for (int nf = 0; nf < 2; ++nf)
#pragma unroll
                for (int c4 = 0; c4 < 4; ++c4) acc[mf][nf][c4] = 0.f;

#pragma unroll 1
        for (int ks = 0; ks < 8; ++ks) {
            const uint32_t ko = (uint32_t)ks * 32u;
            uint32_t aH[2][4], aL[2][4], bh[4], bl[4];
            ldsm4(aH[0], pAh + ko);
            ldsm4(aH[1], pAh + 16u * RSB + ko);
            ldsm4(aL[0], pAl + ko);
            ldsm4(aL[1], pAl + 16u * RSB + ko);
            ldsm4(bh, pBh + ko);
            ldsm4(bl, pBl + ko);
#pragma unroll
            for (int nf = 0; nf < 2; ++nf)
#pragma unroll
                for (int mf = 0; mf < 2; ++mf)
                    mma_bf16(acc[mf][nf], aH[mf], bh[nf], bh[nf + 2]);
#pragma unroll
            for (int nf = 0; nf < 2; ++nf)
#pragma unroll
                for (int mf = 0; mf < 2; ++mf)
                    mma_bf16(acc[mf][nf], aH[mf], bl[nf], bl[nf + 2]);
#pragma unroll
            for (int nf = 0; nf < 2; ++nf)
#pragma unroll
                for (int mf = 0; mf < 2; ++mf)
                    mma_bf16(acc[mf][nf], aL[mf], bh[nf], bh[nf + 2]);
        }

        // ---------------- epilogue: classify once, feed row + column sides
        const float dc = (d != 0) ? 1.0f : 0.0f;
        const uint32_t clsb_s = sb + OFF_CLS + (uint32_t)buf * 64u +
                                (uint32_t)(warp_n * 16 + 2 * (l & 3));
#pragma unroll
        for (int nf = 0; nf < 2; ++nf) {
            unsigned short cw;
            asm volatile("ld.shared.u16 %0, [%1];" : "=h"(cw) : "r"(clsb_s + (uint32_t)nf * 8u));
            const int cj0 = cw & 0xff, cj1 = cw >> 8;
            float cE0 = 0.f, cE1 = 0.f, cN0 = 0.f, cN1 = 0.f, cL0 = 0.f, cL1 = 0.f;
#pragma unroll
            for (int ri = 0; ri < 4; ++ri) {
                float v0 = acc[ri >> 1][nf][(ri & 1) * 2 + 0];
                float v1 = acc[ri >> 1][nf][(ri & 1) * 2 + 1];
                float e0 = ex2f(v0), e1 = ex2f(v1);
                if (cj0 == pc[ri]) { epos[ri] += e0; lsum[ri] += v0;
                                     cE0 += dc * e0; cL0 += dc * v0; }
                else if (cj0 == ncl[ri]) { eneg[ri] += e0; cN0 += dc * e0; }
                if (cj1 == pc[ri]) { epos[ri] += e1; lsum[ri] += v1;
                                     cE1 += dc * e1; cL1 += dc * v1; }
                else if (cj1 == ncl[ri]) { eneg[ri] += e1; cN1 += dc * e1; }
            }
#pragma unroll
            for (int s = 4; s <= 16; s <<= 1) {
                cE0 += __shfl_xor_sync(0xffffffffu, cE0, s);
                cE1 += __shfl_xor_sync(0xffffffffu, cE1, s);
                cN0 += __shfl_xor_sync(0xffffffffu, cN0, s);
                cN1 += __shfl_xor_sync(0xffffffffu, cN1, s);
                cL0 += __shfl_xor_sync(0xffffffffu, cL0, s);
                cL1 += __shfl_xor_sync(0xffffffffu, cL1, s);
            }
            if ((l >> 2) == 0) {   // lanes 0..3
                int col = warp_n * 16 + nf * 8 + 2 * l;
                int base = (warp_m * 64 + col) * 3;
                red[base + 0] = cE0; red[base + 1] = cN0; red[base + 2] = cL0;
                red[base + 3] = cE1; red[base + 4] = cN1; red[base + 5] = cL1;
            }
        }
        __syncthreads();   // red writes visible (unconditional)
        if (d != 0 && tid < 64) {
            float E = red[tid * 3 + 0] + red[(64 + tid) * 3 + 0];
            float N = red[tid * 3 + 1] + red[(64 + tid) * 3 + 1];
            float L = red[tid * 3 + 2] + red[(64 + tid) * 3 + 2];
            g_cpart[d - 1][tj * 64 + tid] = make_float4(E, N, L, 0.f);
        }
        __syncthreads();   // end-of-job (unconditional): red consumed, B[buf] free
    }

    // ---------------- row flush (once per CTA)
#pragma unroll
    for (int ri = 0; ri < 4; ++ri) {
        epos[ri] += __shfl_xor_sync(0xffffffffu, epos[ri], 1);
        epos[ri] += __shfl_xor_sync(0xffffffffu, epos[ri], 2);
        eneg[ri] += __shfl_xor_sync(0xffffffffu, eneg[ri], 1);
        eneg[ri] += __shfl_xor_sync(0xffffffffu, eneg[ri], 2);
        lsum[ri] += __shfl_xor_sync(0xffffffffu, lsum[ri], 1);
        lsum[ri] += __shfl_xor_sync(0xffffffffu, lsum[ri], 2);
    }
    if ((l & 3) == 0) {
#pragma unroll
        for (int ri = 0; ri < 4; ++ri) {
            int row = warp_m * 32 + (ri >> 1) * 16 + (ri & 1) * 8 + (l >> 2);
            red[(row * 4 + warp_n) * 3 + 0] = epos[ri];
            red[(row * 4 + warp_n) * 3 + 1] = eneg[ri];
            red[(row * 4 + warp_n) * 3 + 2] = lsum[ri];
        }
    }
    __syncthreads();
    if (tid < 64) {
        float Ep = 0.f, En = 0.f, Ls = 0.f;
#pragma unroll
        for (int wn = 0; wn < 4; ++wn) {
            Ep += red[(tid * 4 + wn) * 3 + 0];
            En += red[(tid * 4 + wn) * 3 + 1];
            Ls += red[(tid * 4 + wn) * 3 + 2];
        }
        g_rpart[q][x * 64 + tid] = make_float4(Ep, En, Ls, 0.f);
    }
}

// ---------------------------------------------------------------- per-row values
// grid (64, 256): 128 rows per CTA, 2 threads per row, 33 slices each.
__global__ void rowval_kernel() {
    int tid = threadIdx.x;
    int i = blockIdx.x * 128 + (tid >> 1);
    int p = tid & 1;
    float Ep = 0.f, En = 0.f, Ls = 0.f;
#pragma unroll
    for (int s = 0; s < 33; ++s) {
        int sl = p * 33 + s;                 // 0..65
        float4 v = (sl < 2) ? g_rpart[sl][i] : g_cpart[sl - 2][i];
        Ep += v.x; En += v.y; Ls += v.z;
    }
    Ep += __shfl_xor_sync(0xffffffffu, Ep, 1);
    En += __shfl_xor_sync(0xffffffffu, En, 1);
    Ls += __shfl_xor_sync(0xffffffffu, Ls, 1);
    if (p == 0) {
        int ci = g_cls[i];
        int pcnt = g_cnt4[ci ^ 1];
        int ncnt = g_cnt4[ci ^ 2];
        float val = 0.f;
        if (pcnt > 0 && ncnt > 0)
            val = (Ls * 0.6931471805599453f - (float)pcnt * logf(Ep + En)) / (float)pcnt;
        g_rowval[i] = val;
    }
}

// ---------------------------------------------------------------- final sum
__global__ void sum_kernel(float* __restrict__ out) {
    __shared__ float s[256];
    float acc = 0.f;
    for (int i = threadIdx.x; i < B_SZ; i += 256) acc += g_rowval[i];
    s[threadIdx.x] = acc;
    __syncthreads();
    for (int o = 128; o; o >>= 1) {
        if (threadIdx.x < o) s[threadIdx.x] += s[threadIdx.x + o];
        __syncthreads();
    }
    if (threadIdx.x == 0) out[0] = -s[0] / (float)B_SZ;
}

// ---------------------------------------------------------------- launch
extern "C" void kernel_launch(void* const* d_in, const int* in_sizes, int n_in,
                              void* d_out, int out_size) {
    const float* F = (const float*)d_in[0];
    const void* dix = d_in[1];
    const void* tt  = d_in[2];
    const void* tp  = d_in[3];
    float* out = (float*)d_out;

    zero_kernel<<<512, 256>>>();
    detect_kernel<<<1, 256>>>((const long long*)dix);
    prep_kernel<<<(B_SZ * 32) / 256, 256>>>(F, dix, tt, tp);

    cudaFuncSetAttribute(main_kernel, cudaFuncAttributeMaxDynamicSharedMemorySize, SMEM_BYTES);
    main_kernel<<<dim3(128, 2), 256, SMEM_BYTES>>>();

    rowval_kernel<<<64, 256>>>();
    sum_kernel<<<1, 256>>>(out);
}